// round 3
// baseline (speedup 1.0000x reference)
#include <cuda_runtime.h>

#define NT 1024

__device__ __forceinline__ float relu(float x) { return fmaxf(x, 0.0f); }

__constant__ int c_P0[8] = {0, 0, 4, 1, 2, 2, 6, 3};
__constant__ int c_P1[8] = {4, 1, 5, 5, 6, 3, 7, 7};

// All weights cached in shared (one batched prefetch, single DRAM latency exposure).
struct SW {
    float dv_w1[16], dv_b1[16], dv_w2[64], dv_b2[32];
    float dp_w1[16], dp_b1[16], dp_w2[64], dp_b2[32];
    float emb_w[128], emb_b[16];
    float cp_w1[640], cp_b1[20], cp_w2[400], cp_b2[20];
    float cm_w1[4],  cm_b1[4],  cm_w2[80],  cm_b2[20], cm_w3[400], cm_b3[20];
    float cc_w1[160], cc_b1[8], cc_w2[8],  cc_b2[4];
    float q_w1[128], q_b1[16], q_w2[256], q_b2[16], q_w3[128], q_b3[8];
    float mask[56], st[16];
};

__device__ __forceinline__ void cpsh(float* dst, const float* src, int n, int t) {
    if (t < n) dst[t] = src[t];   // all arrays have n <= NT
}

__global__ void __launch_bounds__(NT, 1)
frap_fused_kernel(
    const float* __restrict__ state, int B,
    const float* __restrict__ dv_w1, const float* __restrict__ dv_b1,
    const float* __restrict__ dv_w2, const float* __restrict__ dv_b2,
    const float* __restrict__ dp_w1, const float* __restrict__ dp_b1,
    const float* __restrict__ dp_w2, const float* __restrict__ dp_b2,
    const float* __restrict__ emb_w, const float* __restrict__ emb_b,
    const float* __restrict__ cp_w1, const float* __restrict__ cp_b1,
    const float* __restrict__ cp_w2, const float* __restrict__ cp_b2,
    const float* __restrict__ cm_w1, const float* __restrict__ cm_b1,
    const float* __restrict__ cm_w2, const float* __restrict__ cm_b2,
    const float* __restrict__ cm_w3, const float* __restrict__ cm_b3,
    const float* __restrict__ cc_w1, const float* __restrict__ cc_b1,
    const float* __restrict__ cc_w2, const float* __restrict__ cc_b2,
    const float* __restrict__ q_w1,  const float* __restrict__ q_b1,
    const float* __restrict__ q_w2,  const float* __restrict__ q_b2,
    const float* __restrict__ q_w3,  const float* __restrict__ q_b3,
    const float* __restrict__ mask,
    float4* __restrict__ out, int n4)
{
    __shared__ SW w;
    __shared__ float s_cat[8][8];
    __shared__ float s_d[8][16];
    __shared__ float s_pd[8][16];
    __shared__ float s_z[32][56];
    __shared__ float s_y1[20][56];
    __shared__ float s_y2[20][56];
    __shared__ float s_z0[20][56];
    __shared__ float s_z1[20][56];
    __shared__ float s_z1c[20];
    __shared__ float s_rc1[2][8][56];
    __shared__ float s_rc2[2][56];
    __shared__ float s_rsum[2][8];
    __shared__ float s_h1[2][16];
    __shared__ float s_h2[2][16];
    __shared__ __align__(16) float s_q[2][8];  // [0]=last row, [1]=common

    const int t = threadIdx.x;

    // ---- 0. Batched weight prefetch (all loads independent; one latency exposure) ----
    cpsh(w.dv_w1, dv_w1, 16, t);  cpsh(w.dv_b1, dv_b1, 16, t);
    cpsh(w.dv_w2, dv_w2, 64, t);  cpsh(w.dv_b2, dv_b2, 32, t);
    cpsh(w.dp_w1, dp_w1, 16, t);  cpsh(w.dp_b1, dp_b1, 16, t);
    cpsh(w.dp_w2, dp_w2, 64, t);  cpsh(w.dp_b2, dp_b2, 32, t);
    cpsh(w.emb_w, emb_w, 128, t); cpsh(w.emb_b, emb_b, 16, t);
    cpsh(w.cp_w1, cp_w1, 640, t); cpsh(w.cp_b1, cp_b1, 20, t);
    cpsh(w.cp_w2, cp_w2, 400, t); cpsh(w.cp_b2, cp_b2, 20, t);
    cpsh(w.cm_w1, cm_w1, 4, t);   cpsh(w.cm_b1, cm_b1, 4, t);
    cpsh(w.cm_w2, cm_w2, 80, t);  cpsh(w.cm_b2, cm_b2, 20, t);
    cpsh(w.cm_w3, cm_w3, 400, t); cpsh(w.cm_b3, cm_b3, 20, t);
    cpsh(w.cc_w1, cc_w1, 160, t); cpsh(w.cc_b1, cc_b1, 8, t);
    cpsh(w.cc_w2, cc_w2, 8, t);   cpsh(w.cc_b2, cc_b2, 1, t);
    cpsh(w.q_w1, q_w1, 128, t);   cpsh(w.q_b1, q_b1, 16, t);
    cpsh(w.q_w2, q_w2, 256, t);   cpsh(w.q_b2, q_b2, 16, t);
    cpsh(w.q_w3, q_w3, 128, t);   cpsh(w.q_b3, q_b3, 8, t);
    cpsh(w.mask, mask, 56, t);
    cpsh(w.st, state + (size_t)(B - 1) * 16, 16, t);
    __syncthreads();

    // ---- 1. Per-phase demand MLPs on state[B-1] (8 threads) ----
    if (t < 8) {
        const int p = t;
        const float sv = w.st[p];       // s[:8] -> dv_*
        const float sp = w.st[8 + p];   // s[8:16] -> dp_*
        float h0 = relu(sv * w.dv_w1[p * 2 + 0] + w.dv_b1[p * 2 + 0]);
        float h1 = relu(sv * w.dv_w1[p * 2 + 1] + w.dv_b1[p * 2 + 1]);
        #pragma unroll
        for (int o = 0; o < 4; o++)
            s_cat[p][o] = relu(h0 * w.dv_w2[p * 8 + o * 2 + 0] +
                               h1 * w.dv_w2[p * 8 + o * 2 + 1] + w.dv_b2[p * 4 + o]);
        h0 = relu(sp * w.dp_w1[p * 2 + 0] + w.dp_b1[p * 2 + 0]);
        h1 = relu(sp * w.dp_w1[p * 2 + 1] + w.dp_b1[p * 2 + 1]);
        #pragma unroll
        for (int o = 0; o < 4; o++)
            s_cat[p][4 + o] = relu(h0 * w.dp_w2[p * 8 + o * 2 + 0] +
                                   h1 * w.dp_w2[p * 8 + o * 2 + 1] + w.dp_b2[p * 4 + o]);
    }
    // ---- 5a. Mask chain stage 1+2 fused (independent; overlap with stage 1) ----
    if (t < 20 * 56) {
        const int o = t / 56, pos = t % 56;
        const float m = w.mask[pos];
        float acc = w.cm_b2[o];
        #pragma unroll
        for (int c = 0; c < 4; c++)
            acc += w.cm_w2[o * 4 + c] * relu(w.cm_w1[c] * m + w.cm_b1[c]);
        s_y1[o][pos] = relu(acc);
    } else if (t < 20 * 56 + 96) {
        const int idx = t - 20 * 56;       // 0..95 : tail elements 1024..1119
        const int e = idx + NT;            // not used (20*56=1120 > NT), handled below
        (void)e;
    }
    // tail of the 1120-element stage (elements 1024..1119) on threads 0..95 of a
    // second pass is avoided by using threads 928..1023 here:
    if (t >= NT - 96) {
        const int e = 1024 + (t - (NT - 96));  // 1024..1119
        const int o = e / 56, pos = e % 56;
        const float m = w.mask[pos];
        float acc = w.cm_b2[o];
        #pragma unroll
        for (int c = 0; c < 4; c++)
            acc += w.cm_w2[o * 4 + c] * relu(w.cm_w1[c] * m + w.cm_b1[c]);
        s_y1[o][pos] = relu(acc);
    }
    // common cp-chain (pos-invariant, z=0 path)
    if (t >= 64 && t < 84) {
        const int o = t - 64;
        float acc = w.cp_b2[o];
        #pragma unroll
        for (int c = 0; c < 20; c++) acc += w.cp_w2[o * 20 + c] * relu(w.cp_b1[c]);
        s_z1c[o] = relu(acc);
    }
    __syncthreads();

    // ---- 2. Embedding (128 threads) + 5b. y2 (1120 elements, threads 0..1119 of next pass) ----
    if (t < 128) {
        const int p = t >> 4, k = t & 15;
        float acc = w.emb_b[k];
        #pragma unroll
        for (int j = 0; j < 8; j++) acc += s_cat[p][j] * w.emb_w[k * 8 + j];
        s_d[p][k] = relu(acc);
    }
    // 5b: y2 = relu(cm_w3 . y1 + cm_b3)  — independent of embedding
    for (int idx = t; idx < 20 * 56; idx += NT) {
        const int o = idx / 56, pos = idx % 56;
        float acc = w.cm_b3[o];
        #pragma unroll
        for (int c = 0; c < 20; c++) acc += w.cm_w3[o * 20 + c] * s_y1[c][pos];
        s_y2[o][pos] = relu(acc);
    }
    __syncthreads();

    // ---- 3. Phase-pair demand (128 threads) ----
    if (t < 128) {
        const int q = t >> 4, k = t & 15;
        s_pd[q][k] = s_d[c_P0[q]][k] + s_d[c_P1[q]][k];
    }
    __syncthreads();

    // ---- 4. Build z ((7,8,32) scatter viewed as (32,7,8)), 1792 elements ----
    for (int idx = t; idx < 1792; idx += NT) {
        const int c = idx / 56, pos = idx % 56;
        const int r = idx >> 8, col = (idx >> 5) & 7, k = idx & 31;
        const int j = col;
        const int i = (r < j) ? r : r + 1;
        s_z[c][pos] = (k < 16) ? s_pd[i][k] : s_pd[j][k - 16];
    }
    __syncthreads();

    // ---- 6. cp conv chain (last path), 1120 elements each stage ----
    for (int idx = t; idx < 20 * 56; idx += NT) {
        const int o = idx / 56, pos = idx % 56;
        float acc = w.cp_b1[o];
        #pragma unroll
        for (int c = 0; c < 32; c++) acc += w.cp_w1[o * 32 + c] * s_z[c][pos];
        s_z0[o][pos] = relu(acc);
    }
    __syncthreads();
    for (int idx = t; idx < 20 * 56; idx += NT) {
        const int o = idx / 56, pos = idx % 56;
        float acc = w.cp_b2[o];
        #pragma unroll
        for (int c = 0; c < 20; c++) acc += w.cp_w2[o * 20 + c] * s_z0[c][pos];
        s_z1[o][pos] = relu(acc);
    }
    __syncthreads();

    // ---- 7. r = z1 * y ; cc conv chain, both paths (896 elements) ----
    if (t < 2 * 8 * 56) {
        const int path = t / (8 * 56);
        const int rem = t % (8 * 56);
        const int o = rem / 56, pos = rem % 56;
        float acc = w.cc_b1[o];
        #pragma unroll
        for (int c = 0; c < 20; c++) {
            const float rv = (path ? s_z1c[c] : s_z1[c][pos]) * s_y2[c][pos];
            acc += w.cc_w1[o * 20 + c] * rv;
        }
        s_rc1[path][o][pos] = relu(acc);
    }
    __syncthreads();
    if (t < 2 * 56) {
        const int path = t / 56, pos = t % 56;
        float acc = w.cc_b2[0];
        #pragma unroll
        for (int c = 0; c < 8; c++) acc += w.cc_w2[c] * s_rc1[path][c][pos];
        s_rc2[path][pos] = relu(acc);
    }
    __syncthreads();
    if (t < 16) {
        const int path = t >> 3, ww = t & 7;
        float acc = 0.0f;
        #pragma unroll
        for (int h = 0; h < 7; h++) acc += s_rc2[path][h * 8 + ww];
        s_rsum[path][ww] = acc;
    }
    __syncthreads();

    // ---- 8. Q network, both paths ----
    if (t < 32) {
        const int path = t >> 4, k = t & 15;
        float acc = w.q_b1[k];
        #pragma unroll
        for (int j = 0; j < 8; j++) acc += s_rsum[path][j] * w.q_w1[k * 8 + j];
        s_h1[path][k] = relu(acc);
    }
    __syncthreads();
    if (t < 32) {
        const int path = t >> 4, k = t & 15;
        float acc = w.q_b2[k];
        #pragma unroll
        for (int j = 0; j < 16; j++) acc += s_h1[path][j] * w.q_w2[k * 16 + j];
        s_h2[path][k] = relu(acc);
    }
    __syncthreads();
    if (t < 16) {
        const int path = t >> 3, o = t & 7;
        float acc = w.q_b3[o];
        #pragma unroll
        for (int j = 0; j < 16; j++) acc += s_h2[path][j] * w.q_w3[o * 16 + j];
        s_q[path][o] = relu(acc);
    }
    __syncthreads();

    // ---- 9. Fill output: rows 0..B-2 get common q, row B-1 gets last q ----
    const float4 qc0 = *reinterpret_cast<const float4*>(&s_q[1][0]);
    const float4 qc1 = *reinterpret_cast<const float4*>(&s_q[1][4]);
    const int stride = gridDim.x * NT;
    for (int i = blockIdx.x * NT + t; i < n4 - 2; i += stride)
        out[i] = (i & 1) ? qc1 : qc0;
    if (blockIdx.x == 0 && t < 2) {
        out[n4 - 2 + t] = (t == 0)
            ? *reinterpret_cast<const float4*>(&s_q[0][0])
            : *reinterpret_cast<const float4*>(&s_q[0][4]);
    }
}

extern "C" void kernel_launch(void* const* d_in, const int* in_sizes, int n_in,
                              void* d_out, int out_size) {
    const float* state = (const float*)d_in[0];
    const int B = in_sizes[0] / 16;

    const float* dv_w1 = (const float*)d_in[1];
    const float* dv_b1 = (const float*)d_in[2];
    const float* dv_w2 = (const float*)d_in[3];
    const float* dv_b2 = (const float*)d_in[4];
    const float* dp_w1 = (const float*)d_in[5];
    const float* dp_b1 = (const float*)d_in[6];
    const float* dp_w2 = (const float*)d_in[7];
    const float* dp_b2 = (const float*)d_in[8];
    const float* emb_w = (const float*)d_in[9];
    const float* emb_b = (const float*)d_in[10];
    const float* cp_w1 = (const float*)d_in[11];
    const float* cp_b1 = (const float*)d_in[12];
    const float* cp_w2 = (const float*)d_in[13];
    const float* cp_b2 = (const float*)d_in[14];
    const float* cm_w1 = (const float*)d_in[15];
    const float* cm_b1 = (const float*)d_in[16];
    const float* cm_w2 = (const float*)d_in[17];
    const float* cm_b2 = (const float*)d_in[18];
    const float* cm_w3 = (const float*)d_in[19];
    const float* cm_b3 = (const float*)d_in[20];
    const float* cc_w1 = (const float*)d_in[21];
    const float* cc_b1 = (const float*)d_in[22];
    const float* cc_w2 = (const float*)d_in[23];
    const float* cc_b2 = (const float*)d_in[24];
    const float* q_w1  = (const float*)d_in[25];
    const float* q_b1  = (const float*)d_in[26];
    const float* q_w2  = (const float*)d_in[27];
    const float* q_b2  = (const float*)d_in[28];
    const float* q_w3  = (const float*)d_in[29];
    const float* q_b3  = (const float*)d_in[30];
    const float* mask  = (const float*)d_in[31];

    const int n4 = out_size / 4;
    frap_fused_kernel<<<148, NT>>>(
        state, B,
        dv_w1, dv_b1, dv_w2, dv_b2,
        dp_w1, dp_b1, dp_w2, dp_b2,
        emb_w, emb_b,
        cp_w1, cp_b1, cp_w2, cp_b2,
        cm_w1, cm_b1, cm_w2, cm_b2, cm_w3, cm_b3,
        cc_w1, cc_b1, cc_w2, cc_b2,
        q_w1, q_b1, q_w2, q_b2, q_w3, q_b3,
        mask,
        (float4*)d_out, n4);
}

// round 4
// speedup vs baseline: 1.6344x; 1.6344x over previous
#include <cuda_runtime.h>

#define NT 256

__device__ __forceinline__ float relu(float x) { return fmaxf(x, 0.0f); }

__constant__ int c_P0[8] = {0, 0, 4, 1, 2, 2, 6, 3};
__constant__ int c_P1[8] = {4, 1, 5, 5, 6, 3, 7, 7};

// All weights cached in shared (cp.async batched prefetch, single wait).
struct SW {
    float dv_w1[16], dv_b1[16], dv_w2[64], dv_b2[32];
    float dp_w1[16], dp_b1[16], dp_w2[64], dp_b2[32];
    float emb_w[128], emb_b[16];
    float cp_w1[640], cp_b1[20], cp_w2[400], cp_b2[20];
    float cm_w1[4],  cm_b1[4],  cm_w2[80],  cm_b2[20], cm_w3[400], cm_b3[20];
    float cc_w1[160], cc_b1[8], cc_w2[8],  cc_b2[4];
    float q_w1[128], q_b1[16], q_w2[256], q_b2[16], q_w3[128], q_b3[8];
    float mask[56], st[16];
};

__device__ __forceinline__ void cp4(float* s, const float* g) {
    unsigned sa = (unsigned)__cvta_generic_to_shared(s);
    asm volatile("cp.async.ca.shared.global [%0], [%1], 4;" :: "r"(sa), "l"(g));
}
__device__ __forceinline__ void cpsh(float* dst, const float* src, int n, int t) {
    for (int i = t; i < n; i += NT) cp4(dst + i, src + i);
}

__global__ void __launch_bounds__(NT, 1)
frap_fused_kernel(
    const float* __restrict__ state, int B,
    const float* __restrict__ dv_w1, const float* __restrict__ dv_b1,
    const float* __restrict__ dv_w2, const float* __restrict__ dv_b2,
    const float* __restrict__ dp_w1, const float* __restrict__ dp_b1,
    const float* __restrict__ dp_w2, const float* __restrict__ dp_b2,
    const float* __restrict__ emb_w, const float* __restrict__ emb_b,
    const float* __restrict__ cp_w1, const float* __restrict__ cp_b1,
    const float* __restrict__ cp_w2, const float* __restrict__ cp_b2,
    const float* __restrict__ cm_w1, const float* __restrict__ cm_b1,
    const float* __restrict__ cm_w2, const float* __restrict__ cm_b2,
    const float* __restrict__ cm_w3, const float* __restrict__ cm_b3,
    const float* __restrict__ cc_w1, const float* __restrict__ cc_b1,
    const float* __restrict__ cc_w2, const float* __restrict__ cc_b2,
    const float* __restrict__ q_w1,  const float* __restrict__ q_b1,
    const float* __restrict__ q_w2,  const float* __restrict__ q_b2,
    const float* __restrict__ q_w3,  const float* __restrict__ q_b3,
    const float* __restrict__ mask,
    float4* __restrict__ out, int n4)
{
    __shared__ SW w;
    __shared__ float s_cat[8][8];
    __shared__ float s_d[8][16];
    __shared__ float s_z[32][56];
    __shared__ float s_y1[20][56];
    __shared__ float s_y2[20][56];
    __shared__ float s_z0[20][56];
    __shared__ float s_z1[20][56];
    __shared__ float s_z1c[20];
    __shared__ float s_rc1[2][8][56];
    __shared__ float s_rc2[2][56];
    __shared__ float s_rsum[2][8];
    __shared__ float s_h1[2][16];
    __shared__ float s_h2[2][16];
    __shared__ __align__(16) float s_q[2][8];  // [0]=last row, [1]=common

    const int t = threadIdx.x;

    // ---- 0. cp.async weight prefetch: everything in flight, one wait ----
    cpsh(w.dv_w1, dv_w1, 16, t);  cpsh(w.dv_b1, dv_b1, 16, t);
    cpsh(w.dv_w2, dv_w2, 64, t);  cpsh(w.dv_b2, dv_b2, 32, t);
    cpsh(w.dp_w1, dp_w1, 16, t);  cpsh(w.dp_b1, dp_b1, 16, t);
    cpsh(w.dp_w2, dp_w2, 64, t);  cpsh(w.dp_b2, dp_b2, 32, t);
    cpsh(w.emb_w, emb_w, 128, t); cpsh(w.emb_b, emb_b, 16, t);
    cpsh(w.cp_w1, cp_w1, 640, t); cpsh(w.cp_b1, cp_b1, 20, t);
    cpsh(w.cp_w2, cp_w2, 400, t); cpsh(w.cp_b2, cp_b2, 20, t);
    cpsh(w.cm_w1, cm_w1, 4, t);   cpsh(w.cm_b1, cm_b1, 4, t);
    cpsh(w.cm_w2, cm_w2, 80, t);  cpsh(w.cm_b2, cm_b2, 20, t);
    cpsh(w.cm_w3, cm_w3, 400, t); cpsh(w.cm_b3, cm_b3, 20, t);
    cpsh(w.cc_w1, cc_w1, 160, t); cpsh(w.cc_b1, cc_b1, 8, t);
    cpsh(w.cc_w2, cc_w2, 8, t);   cpsh(w.cc_b2, cc_b2, 1, t);
    cpsh(w.q_w1, q_w1, 128, t);   cpsh(w.q_b1, q_b1, 16, t);
    cpsh(w.q_w2, q_w2, 256, t);   cpsh(w.q_b2, q_b2, 16, t);
    cpsh(w.q_w3, q_w3, 128, t);   cpsh(w.q_b3, q_b3, 8, t);
    cpsh(w.mask, mask, 56, t);
    cpsh(w.st, state + (size_t)(B - 1) * 16, 16, t);
    asm volatile("cp.async.commit_group;");
    asm volatile("cp.async.wait_group 0;");
    __syncthreads();

    // ==== Stage A: cat (t<8) | z1c (t in [8,28)) | y1 (t in [32,256)) ====
    if (t < 8) {
        const int p = t;
        const float sv = w.st[p];
        const float sp = w.st[8 + p];
        float h0 = relu(sv * w.dv_w1[p * 2 + 0] + w.dv_b1[p * 2 + 0]);
        float h1 = relu(sv * w.dv_w1[p * 2 + 1] + w.dv_b1[p * 2 + 1]);
        #pragma unroll
        for (int o = 0; o < 4; o++)
            s_cat[p][o] = relu(h0 * w.dv_w2[p * 8 + o * 2 + 0] +
                               h1 * w.dv_w2[p * 8 + o * 2 + 1] + w.dv_b2[p * 4 + o]);
        h0 = relu(sp * w.dp_w1[p * 2 + 0] + w.dp_b1[p * 2 + 0]);
        h1 = relu(sp * w.dp_w1[p * 2 + 1] + w.dp_b1[p * 2 + 1]);
        #pragma unroll
        for (int o = 0; o < 4; o++)
            s_cat[p][4 + o] = relu(h0 * w.dp_w2[p * 8 + o * 2 + 0] +
                                   h1 * w.dp_w2[p * 8 + o * 2 + 1] + w.dp_b2[p * 4 + o]);
    } else if (t < 28) {
        const int o = t - 8;
        float acc = w.cp_b2[o];
        #pragma unroll
        for (int c = 0; c < 20; c++) acc += w.cp_w2[o * 20 + c] * relu(w.cp_b1[c]);
        s_z1c[o] = relu(acc);
    } else if (t >= 32) {
        // y1: (pos, group-of-5 outputs); 224 threads
        const int idx = t - 32;
        const int pos = idx % 56, og = idx / 56;
        const float m = w.mask[pos];
        float hid[4];
        #pragma unroll
        for (int c = 0; c < 4; c++) hid[c] = relu(w.cm_w1[c] * m + w.cm_b1[c]);
        #pragma unroll
        for (int u = 0; u < 5; u++) {
            const int o = og * 5 + u;
            float acc = w.cm_b2[o];
            #pragma unroll
            for (int c = 0; c < 4; c++) acc += w.cm_w2[o * 4 + c] * hid[c];
            s_y1[o][pos] = relu(acc);
        }
    }
    __syncthreads();

    // ==== Stage B: embedding d (t<128) ====
    if (t < 128) {
        const int p = t >> 4, k = t & 15;
        float acc = w.emb_b[k];
        #pragma unroll
        for (int j = 0; j < 8; j++) acc += s_cat[p][j] * w.emb_w[k * 8 + j];
        s_d[p][k] = relu(acc);
    }
    __syncthreads();

    // ==== Stage C: z (all threads, direct from d) then y2 (t<224, reuse-tiled) ====
    #pragma unroll
    for (int rep = 0; rep < 7; rep++) {
        const int idx = t + rep * NT;   // 1792 = 7*256 exactly
        const int pos = idx % 56;
        const int r = idx >> 8, col = (idx >> 5) & 7, k = idx & 31;
        const int i = (r < col) ? r : r + 1;
        const int sel = (k < 16) ? i : col;
        const int kk = k & 15;
        s_z[idx / 56][pos] = s_d[c_P0[sel]][kk] + s_d[c_P1[sel]][kk];
    }
    if (t < 224) {
        const int pos = t % 56, og = t / 56;
        float acc[5];
        #pragma unroll
        for (int u = 0; u < 5; u++) acc[u] = w.cm_b3[og * 5 + u];
        #pragma unroll
        for (int c = 0; c < 20; c++) {
            const float v = s_y1[c][pos];
            #pragma unroll
            for (int u = 0; u < 5; u++) acc[u] += w.cm_w3[(og * 5 + u) * 20 + c] * v;
        }
        #pragma unroll
        for (int u = 0; u < 5; u++) s_y2[og * 5 + u][pos] = relu(acc[u]);
    }
    __syncthreads();

    // ==== Stage D: z0 = conv(z, cp_w1) (t<224, reuse-tiled) ====
    if (t < 224) {
        const int pos = t % 56, og = t / 56;
        float acc[5];
        #pragma unroll
        for (int u = 0; u < 5; u++) acc[u] = w.cp_b1[og * 5 + u];
        #pragma unroll
        for (int c = 0; c < 32; c++) {
            const float v = s_z[c][pos];
            #pragma unroll
            for (int u = 0; u < 5; u++) acc[u] += w.cp_w1[(og * 5 + u) * 32 + c] * v;
        }
        #pragma unroll
        for (int u = 0; u < 5; u++) s_z0[og * 5 + u][pos] = relu(acc[u]);
    }
    __syncthreads();

    // ==== Stage E: z1 = conv(z0, cp_w2) (t<224, reuse-tiled) ====
    if (t < 224) {
        const int pos = t % 56, og = t / 56;
        float acc[5];
        #pragma unroll
        for (int u = 0; u < 5; u++) acc[u] = w.cp_b2[og * 5 + u];
        #pragma unroll
        for (int c = 0; c < 20; c++) {
            const float v = s_z0[c][pos];
            #pragma unroll
            for (int u = 0; u < 5; u++) acc[u] += w.cp_w2[(og * 5 + u) * 20 + c] * v;
        }
        #pragma unroll
        for (int u = 0; u < 5; u++) s_z1[og * 5 + u][pos] = relu(acc[u]);
    }
    __syncthreads();

    // ==== Stage F: rc1 both paths (t<224: pos x 2-output groups x 2 paths) ====
    if (t < 224) {
        // 224 threads = 56 pos * 4 og ; og covers 2 of 8 outputs, both paths
        const int pos = t % 56, og = t / 56;
        float acc0[2], acc1[2];
        #pragma unroll
        for (int u = 0; u < 2; u++) { acc0[u] = w.cc_b1[og * 2 + u]; acc1[u] = acc0[u]; }
        #pragma unroll
        for (int c = 0; c < 20; c++) {
            const float ym = s_y2[c][pos];
            const float rv0 = s_z1[c][pos] * ym;   // last path
            const float rv1 = s_z1c[c] * ym;       // common path
            #pragma unroll
            for (int u = 0; u < 2; u++) {
                const float wv = w.cc_w1[(og * 2 + u) * 20 + c];
                acc0[u] += wv * rv0;
                acc1[u] += wv * rv1;
            }
        }
        #pragma unroll
        for (int u = 0; u < 2; u++) {
            s_rc1[0][og * 2 + u][pos] = relu(acc0[u]);
            s_rc1[1][og * 2 + u][pos] = relu(acc1[u]);
        }
    }
    __syncthreads();

    // ==== Stage G: tail in one warp (rc2 -> rsum -> q1 -> q2 -> q3) ====
    if (t < 32) {
        for (int i = t; i < 112; i += 32) {
            const int path = i / 56, pos = i % 56;
            float acc = w.cc_b2[0];
            #pragma unroll
            for (int c = 0; c < 8; c++) acc += w.cc_w2[c] * s_rc1[path][c][pos];
            s_rc2[path][pos] = relu(acc);
        }
        __syncwarp();
        if (t < 16) {
            const int path = t >> 3, ww = t & 7;
            float acc = 0.0f;
            #pragma unroll
            for (int h = 0; h < 7; h++) acc += s_rc2[path][h * 8 + ww];
            s_rsum[path][ww] = acc;
        }
        __syncwarp();
        {
            const int path = t >> 4, k = t & 15;
            float acc = w.q_b1[k];
            #pragma unroll
            for (int j = 0; j < 8; j++) acc += s_rsum[path][j] * w.q_w1[k * 8 + j];
            s_h1[path][k] = relu(acc);
        }
        __syncwarp();
        {
            const int path = t >> 4, k = t & 15;
            float acc = w.q_b2[k];
            #pragma unroll
            for (int j = 0; j < 16; j++) acc += s_h1[path][j] * w.q_w2[k * 16 + j];
            s_h2[path][k] = relu(acc);
        }
        __syncwarp();
        if (t < 16) {
            const int path = t >> 3, o = t & 7;
            float acc = w.q_b3[o];
            #pragma unroll
            for (int j = 0; j < 16; j++) acc += s_h2[path][j] * w.q_w3[o * 16 + j];
            s_q[path][o] = relu(acc);
        }
    }
    __syncthreads();

    // ==== Fill output: rows 0..B-2 common q, row B-1 last q ====
    const float4 qc0 = *reinterpret_cast<const float4*>(&s_q[1][0]);
    const float4 qc1 = *reinterpret_cast<const float4*>(&s_q[1][4]);
    const int stride = gridDim.x * NT;
    for (int i = blockIdx.x * NT + t; i < n4 - 2; i += stride)
        out[i] = (i & 1) ? qc1 : qc0;
    if (blockIdx.x == 0 && t < 2) {
        out[n4 - 2 + t] = (t == 0)
            ? *reinterpret_cast<const float4*>(&s_q[0][0])
            : *reinterpret_cast<const float4*>(&s_q[0][4]);
    }
}

extern "C" void kernel_launch(void* const* d_in, const int* in_sizes, int n_in,
                              void* d_out, int out_size) {
    const float* state = (const float*)d_in[0];
    const int B = in_sizes[0] / 16;

    const float* dv_w1 = (const float*)d_in[1];
    const float* dv_b1 = (const float*)d_in[2];
    const float* dv_w2 = (const float*)d_in[3];
    const float* dv_b2 = (const float*)d_in[4];
    const float* dp_w1 = (const float*)d_in[5];
    const float* dp_b1 = (const float*)d_in[6];
    const float* dp_w2 = (const float*)d_in[7];
    const float* dp_b2 = (const float*)d_in[8];
    const float* emb_w = (const float*)d_in[9];
    const float* emb_b = (const float*)d_in[10];
    const float* cp_w1 = (const float*)d_in[11];
    const float* cp_b1 = (const float*)d_in[12];
    const float* cp_w2 = (const float*)d_in[13];
    const float* cp_b2 = (const float*)d_in[14];
    const float* cm_w1 = (const float*)d_in[15];
    const float* cm_b1 = (const float*)d_in[16];
    const float* cm_w2 = (const float*)d_in[17];
    const float* cm_b2 = (const float*)d_in[18];
    const float* cm_w3 = (const float*)d_in[19];
    const float* cm_b3 = (const float*)d_in[20];
    const float* cc_w1 = (const float*)d_in[21];
    const float* cc_b1 = (const float*)d_in[22];
    const float* cc_w2 = (const float*)d_in[23];
    const float* cc_b2 = (const float*)d_in[24];
    const float* q_w1  = (const float*)d_in[25];
    const float* q_b1  = (const float*)d_in[26];
    const float* q_w2  = (const float*)d_in[27];
    const float* q_b2  = (const float*)d_in[28];
    const float* q_w3  = (const float*)d_in[29];
    const float* q_b3  = (const float*)d_in[30];
    const float* mask  = (const float*)d_in[31];

    const int n4 = out_size / 4;
    frap_fused_kernel<<<148, NT>>>(
        state, B,
        dv_w1, dv_b1, dv_w2, dv_b2,
        dp_w1, dp_b1, dp_w2, dp_b2,
        emb_w, emb_b,
        cp_w1, cp_b1, cp_w2, cp_b2,
        cm_w1, cm_b1, cm_w2, cm_b2, cm_w3, cm_b3,
        cc_w1, cc_b1, cc_w2, cc_b2,
        q_w1, q_b1, q_w2, q_b2, q_w3, q_b3,
        mask,
        (float4*)d_out, n4);
}